// round 12
// baseline (speedup 1.0000x reference)
#include <cuda_runtime.h>

// ---------------------------------------------------------------------------
// SimpleYOLOLoss on GB300 — single fused kernel, single wave (672 blocks).
// R7 structure (proven optimum) + micro-opts:
//  - target phase: 512 blocks; each warp handles TWO same-level items
//    (shared level constants, MLP 4, pipelined shfl chains). adj-logit loads
//    split across lanes 0 and 1 (parallel latency), combined via shfl.
//  - cls phase: 160 streaming blocks (L0: 128 blocks x 16 iters; one block
//    per batch covers L1+L2+L3).
//  - last-block finalize + reset (graph-replay safe).
// ---------------------------------------------------------------------------

#define FULL_MASK 0xffffffffu

static constexpr int BATCH = 32;
static constexpr int NTGT  = 64;

static constexpr int TGT_BLOCKS = 512;        // 16 items/block, 2 per warp
static constexpr int CLS_BLOCKS = 128 + 32;   // L0 + combined(L1,L2,L3)
static constexpr int TOTAL_BLOCKS = TGT_BLOCKS + CLS_BLOCKS;  // 672

__device__ double       g_S[BATCH];   // per-batch sum over levels of base mean
__device__ int          g_cnt[BATCH]; // valid targets per batch
__device__ double       g_adj;
__device__ double       g_box;
__device__ double       g_dfl;
__device__ unsigned int g_arrive;

__global__ void __launch_bounds__(256) yolo_fused_kernel(
    const float* __restrict__ c0, const float* __restrict__ c1,
    const float* __restrict__ c2, const float* __restrict__ c3,
    const float* __restrict__ r0, const float* __restrict__ r1,
    const float* __restrict__ r2, const float* __restrict__ r3,
    const float* __restrict__ tg,
    float* __restrict__ out)
{
    const int tid = threadIdx.x;

    if (blockIdx.x < TGT_BLOCKS) {
        // ------------------- per-target term: 2 items per warp ------------
        __shared__ double s_acc[3];
        __shared__ int    s_cnt;
        if (tid < 3) s_acc[tid] = 0.0;
        if (tid == 3) s_cnt = 0;
        __syncthreads();

        const int w    = tid >> 5;
        const int lane = tid & 31;
        const int bi   = blockIdx.x;
        const int b    = bi >> 4;                 // 16 blocks per batch
        const int n0   = (bi & 15) << 2;          // 4 targets per block
        const int lvl  = w & 3;
        const int nA   = n0 + (w >> 2);           // warp's first target
        // second target is nA + 2

        const float s     = (float)(8 << lvl);
        const float inv_s = 1.0f / s;             // exact (power of two)
        const int   Wl    = 128 >> lvl;
        const int   HW    = Wl * Wl;
        const float invHW = 1.0f / (float)HW;     // exact (power of two)
        const float* cp = (lvl == 0) ? c0 : (lvl == 1) ? c1 : (lvl == 2) ? c2 : c3;
        const float* rp = (lvl == 0) ? r0 : (lvl == 1) ? r1 : (lvl == 2) ? r2 : r3;

        // ---- load both targets (broadcast loads, independent) ----
        const float* tpA = tg + (size_t)(b * NTGT + nA) * 5;
        const float* tpB = tpA + 10;              // nB = nA + 2
        float tA0 = __ldg(tpA + 0), aX1 = __ldg(tpA + 1), aY1 = __ldg(tpA + 2),
              aX2 = __ldg(tpA + 3), aY2 = __ldg(tpA + 4);
        float tB0 = __ldg(tpB + 0), bX1 = __ldg(tpB + 1), bY1 = __ldg(tpB + 2),
              bX2 = __ldg(tpB + 3), bY2 = __ldg(tpB + 4);
        bool vA = (tA0 >= 0.0f);
        bool vB = (tB0 >= 0.0f);

        float cxA = (aX1 + aX2) * 0.5f, cyA = (aY1 + aY2) * 0.5f;
        float cxB = (bX1 + bX2) * 0.5f, cyB = (bY1 + bY2) * 0.5f;

        int gxA = min(max((int)(cxA * inv_s), 0), Wl - 1);
        int gyA = min(max((int)(cyA * inv_s), 0), Wl - 1);
        int gxB = min(max((int)(cxB * inv_s), 0), Wl - 1);
        int gyB = min(max((int)(cyB * inv_s), 0), Wl - 1);
        if (!vA) { gxA = 0; gyA = 0; }            // safe addresses when invalid
        if (!vB) { gxB = 0; gyB = 0; }

        const int cellA = gyA * Wl + gxA;
        const int cellB = gyB * Wl + gxB;

        // ---- issue all 4 gathers (MLP 4) ----
        const float* rbA = rp + (size_t)b * 64 * HW + (size_t)cellA;
        const float* rbB = rp + (size_t)b * 64 * HW + (size_t)cellB;
        float pA0 = rbA[(size_t)lane * HW];
        float pA1 = rbA[(size_t)(lane + 32) * HW];
        float pB0 = rbB[(size_t)lane * HW];
        float pB1 = rbB[(size_t)(lane + 32) * HW];

        // ---- adj logits: lane 0 -> item A, lane 1 -> item B (parallel) ----
        int cidA = (int)fmaxf(tA0, 0.0f);
        int cidB = (int)fmaxf(tB0, 0.0f);
        float adj_part = 0.0f;
        if (lane < 2) {
            int   cell = (lane == 0) ? cellA : cellB;
            int   cid  = (lane == 0) ? cidA  : cidB;
            bool  v    = (lane == 0) ? vA    : vB;
            const float* lp = cp + ((size_t)b * HW + (size_t)cell) * 4;
            float l0 = lp[0];
            float lc = lp[cid];
            adj_part = v ? (l0 - lc) * invHW : 0.0f;
        }

        // ---- treg values ----
        float trA0 = (cxA - (float)gxA * s) * inv_s;
        float trA1 = (cyA - (float)gyA * s) * inv_s;
        float trA2 = (aX2 - aX1) * inv_s;
        float trA3 = (aY2 - aY1) * inv_s;
        float trB0 = (cxB - (float)gxB * s) * inv_s;
        float trB1 = (cyB - (float)gyB * s) * inv_s;
        float trB2 = (bX2 - bX1) * inv_s;
        float trB3 = (bY2 - bY1) * inv_s;

        float selA0 = (lane < 16) ? trA0 : trA1;
        float selA1 = (lane < 16) ? trA2 : trA3;
        float selB0 = (lane < 16) ? trB0 : trB1;
        float selB1 = (lane < 16) ? trB2 : trB3;

        // ---- dfl sums (two independent chains pipeline) ----
        float dA = fabsf(pA0 - selA0) + fabsf(pA1 - selA1);
        float dB = fabsf(pB0 - selB0) + fabsf(pB1 - selB1);
        #pragma unroll
        for (int o = 16; o > 0; o >>= 1) {
            dA += __shfl_xor_sync(FULL_MASK, dA, o);
            dB += __shfl_xor_sync(FULL_MASK, dB, o);
        }

        // ---- 16-lane segmented sums (four independent chains) ----
        float qA0 = pA0, qA1 = pA1, qB0 = pB0, qB1 = pB1;
        #pragma unroll
        for (int o = 8; o > 0; o >>= 1) {
            qA0 += __shfl_xor_sync(FULL_MASK, qA0, o);
            qA1 += __shfl_xor_sync(FULL_MASK, qA1, o);
            qB0 += __shfl_xor_sync(FULL_MASK, qB0, o);
            qB1 += __shfl_xor_sync(FULL_MASK, qB1, o);
        }
        float mA1 = __shfl_sync(FULL_MASK, qA0, 16);
        float mA3 = __shfl_sync(FULL_MASK, qA1, 16);
        float mB1 = __shfl_sync(FULL_MASK, qB0, 16);
        float mB3 = __shfl_sync(FULL_MASK, qB1, 16);

        // combine adj partials (lanes 0 and 1) into lane 0
        adj_part += __shfl_xor_sync(FULL_MASK, adj_part, 1);

        if (lane == 0) {
            const float i16 = 1.0f / 16.0f;
            float box = 0.0f, dfl = 0.0f;
            int   cnt = 0;
            if (vA) {
                box += (fabsf(qA0 * i16 - trA0) + fabsf(mA1 * i16 - trA1) +
                        fabsf(qA1 * i16 - trA2) + fabsf(mA3 * i16 - trA3)) * 0.25f;
                dfl += dA * (1.0f / 64.0f);
                cnt++;
            }
            if (vB) {
                box += (fabsf(qB0 * i16 - trB0) + fabsf(mB1 * i16 - trB1) +
                        fabsf(qB1 * i16 - trB2) + fabsf(mB3 * i16 - trB3)) * 0.25f;
                dfl += dB * (1.0f / 64.0f);
                cnt++;
            }
            if (cnt) {
                atomicAdd(&s_acc[0], (double)adj_part);
                atomicAdd(&s_acc[1], (double)box);
                atomicAdd(&s_acc[2], (double)dfl);
                if (lvl == 0) atomicAdd(&s_cnt, cnt);
            }
        }
        __syncthreads();
        if (tid == 0) {
            atomicAdd(&g_adj, s_acc[0]);
            atomicAdd(&g_box, s_acc[1]);
            atomicAdd(&g_dfl, s_acc[2]);
            if (s_cnt) atomicAdd(&g_cnt[b], s_cnt);
        }
    } else {
        // ------------- cls base term (exact R7 streaming layout) ----------
        int cb = blockIdx.x - TGT_BLOCKS;

        auto rowval = [](const float4 v) -> float {
            float m  = fmaxf(fmaxf(v.x, v.y), fmaxf(v.z, v.w));
            float se = __expf(v.x - m) + __expf(v.y - m) +
                       __expf(v.z - m) + __expf(v.w - m);
            return (m + __logf(se)) - v.x;
        };

        float scaled;
        int b;
        if (cb < 128) {
            b = cb >> 2;
            const float4* base = reinterpret_cast<const float4*>(c0) +
                                 (size_t)b * 16384 + (size_t)(cb & 3) * 4096 + tid;
            float acc = 0.0f;
            #pragma unroll
            for (int i = 0; i < 16; i++)
                acc += rowval(base[(size_t)i * 256]);
            scaled = acc * (1.0f / 16384.0f);
        } else {
            b = cb - 128;
            const float4* b1 = reinterpret_cast<const float4*>(c1) + (size_t)b * 4096 + tid;
            const float4* b2 = reinterpret_cast<const float4*>(c2) + (size_t)b * 1024 + tid;
            const float4* b3 = reinterpret_cast<const float4*>(c3) + (size_t)b * 256  + tid;
            float a1 = 0.0f, a2 = 0.0f, a3;
            #pragma unroll
            for (int i = 0; i < 16; i++)
                a1 += rowval(b1[(size_t)i * 256]);
            #pragma unroll
            for (int i = 0; i < 4; i++)
                a2 += rowval(b2[(size_t)i * 256]);
            a3 = rowval(b3[0]);
            scaled = a1 * (1.0f / 4096.0f) + a2 * (1.0f / 1024.0f)
                   + a3 * (1.0f / 256.0f);
        }

        #pragma unroll
        for (int o = 16; o > 0; o >>= 1)
            scaled += __shfl_xor_sync(FULL_MASK, scaled, o);

        __shared__ float wsum[8];
        int wid = tid >> 5;
        if ((tid & 31) == 0) wsum[wid] = scaled;
        __syncthreads();
        if (tid == 0) {
            double ssum = 0.0;
            #pragma unroll
            for (int i = 0; i < 8; i++) ssum += (double)wsum[i];
            atomicAdd(&g_S[b], ssum);
        }
    }

    // ------------------- last-block finalize + reset -------------------
    __shared__ bool is_last;
    __threadfence();
    if (tid == 0) {
        unsigned int v = atomicAdd(&g_arrive, 1u);
        is_last = (v == (unsigned)(TOTAL_BLOCKS - 1));
    }
    __syncthreads();

    if (is_last) {
        __threadfence();   // acquire: see all other blocks' accumulator writes
        if (tid == 0) {
            double cls = g_adj;
            #pragma unroll
            for (int b2 = 0; b2 < BATCH; b2++)
                cls += (double)g_cnt[b2] * g_S[b2];
            float clsf = (float)cls;
            float boxf = (float)g_box;
            float dflf = (float)g_dfl;
            out[0] = 0.3f * clsf + 8.0f * boxf + 1.5f * dflf;
            out[1] = clsf;
            out[2] = boxf;
            out[3] = dflf;
        }
        __syncthreads();   // output computed before anyone resets state
        if (tid < BATCH)     { g_S[tid] = 0.0; g_cnt[tid] = 0; }
        if (tid == BATCH)      g_adj = 0.0;
        if (tid == BATCH + 1)  g_box = 0.0;
        if (tid == BATCH + 2)  g_dfl = 0.0;
        if (tid == BATCH + 3)  g_arrive = 0u;
    }
}

extern "C" void kernel_launch(void* const* d_in, const int* in_sizes, int n_in,
                              void* d_out, int out_size)
{
    // Map inputs by element count (order-agnostic). Ambiguous pairs resolved
    // by first-occurrence (cls precedes its reg twin in both grouped and
    // interleaved metadata orders).
    const float *c0 = nullptr, *c1 = nullptr, *c2 = nullptr, *c3 = nullptr;
    const float *r0 = nullptr, *r1 = nullptr, *r2 = nullptr, *r3 = nullptr;
    const float *tg = nullptr;
    int seen2097152 = 0, seen524288 = 0;

    for (int i = 0; i < n_in; i++) {
        const float* p = (const float*)d_in[i];
        switch (in_sizes[i]) {
            case 33554432: r0 = p; break;
            case 8388608:  r1 = p; break;
            case 131072:   c2 = p; break;
            case 32768:    c3 = p; break;
            case 10240:    tg = p; break;
            case 2097152:
                if (seen2097152++ == 0) c0 = p; else r2 = p;
                break;
            case 524288:
                if (seen524288++ == 0) c1 = p; else r3 = p;
                break;
            default: break;
        }
    }

    float* out = (float*)d_out;
    yolo_fused_kernel<<<TOTAL_BLOCKS, 256>>>(c0, c1, c2, c3,
                                             r0, r1, r2, r3, tg, out);
}

// round 13
// speedup vs baseline: 1.1552x; 1.1552x over previous
#include <cuda_runtime.h>

// ---------------------------------------------------------------------------
// SimpleYOLOLoss on GB300 — single fused kernel, single wave (672 blocks).
// EXACT R7 (best measured: 14.848 us, rel_err 2.1e-7).
//  - target phase: 512 blocks; each warp handles TWO same-level items
//    (same (b, lvl), targets n and n+2) -> shared level constants, MLP 4,
//    interleaved shuffle-reduction chains, early adj-logit prefetch.
//  - cls phase: 160 streaming blocks (L0: 128 blocks/16 iters; one block per
//    batch covers L1+L2+L3).
//  - last-block finalize + reset (graph-replay safe).
// ---------------------------------------------------------------------------

#define FULL_MASK 0xffffffffu

static constexpr int BATCH = 32;
static constexpr int NTGT  = 64;

static constexpr int TGT_BLOCKS = 512;        // 16 items/block, 2 per warp
static constexpr int CLS_BLOCKS = 128 + 32;   // L0 + combined(L1,L2,L3)
static constexpr int TOTAL_BLOCKS = TGT_BLOCKS + CLS_BLOCKS;  // 672

__device__ double       g_S[BATCH];   // per-batch sum over levels of base mean
__device__ int          g_cnt[BATCH]; // valid targets per batch
__device__ double       g_adj;
__device__ double       g_box;
__device__ double       g_dfl;
__device__ unsigned int g_arrive;

__global__ void __launch_bounds__(256) yolo_fused_kernel(
    const float* __restrict__ c0, const float* __restrict__ c1,
    const float* __restrict__ c2, const float* __restrict__ c3,
    const float* __restrict__ r0, const float* __restrict__ r1,
    const float* __restrict__ r2, const float* __restrict__ r3,
    const float* __restrict__ tg,
    float* __restrict__ out)
{
    const int tid = threadIdx.x;

    if (blockIdx.x < TGT_BLOCKS) {
        // ------------------- per-target term: 2 items per warp ------------
        __shared__ double s_acc[3];
        __shared__ int    s_cnt;
        if (tid < 3) s_acc[tid] = 0.0;
        if (tid == 3) s_cnt = 0;
        __syncthreads();

        const int w    = tid >> 5;
        const int lane = tid & 31;
        const int bi   = blockIdx.x;
        const int b    = bi >> 4;                 // 16 blocks per batch
        const int n0   = (bi & 15) << 2;          // 4 targets per block
        const int lvl  = w & 3;
        const int nA   = n0 + (w >> 2);           // warp's first target
        // second target is nA + 2

        const float s     = (float)(8 << lvl);
        const float inv_s = 1.0f / s;             // exact (power of two)
        const int   Wl    = 128 >> lvl;
        const int   HW    = Wl * Wl;
        const float invHW = 1.0f / (float)HW;     // exact (power of two)
        const float* cp = (lvl == 0) ? c0 : (lvl == 1) ? c1 : (lvl == 2) ? c2 : c3;
        const float* rp = (lvl == 0) ? r0 : (lvl == 1) ? r1 : (lvl == 2) ? r2 : r3;

        // ---- load both targets (broadcast loads, independent) ----
        const float* tpA = tg + (size_t)(b * NTGT + nA) * 5;
        const float* tpB = tpA + 10;              // nB = nA + 2
        float tA0 = tpA[0], aX1 = tpA[1], aY1 = tpA[2], aX2 = tpA[3], aY2 = tpA[4];
        float tB0 = tpB[0], bX1 = tpB[1], bY1 = tpB[2], bX2 = tpB[3], bY2 = tpB[4];
        bool vA = (tA0 >= 0.0f);
        bool vB = (tB0 >= 0.0f);

        float cxA = (aX1 + aX2) * 0.5f, cyA = (aY1 + aY2) * 0.5f;
        float cxB = (bX1 + bX2) * 0.5f, cyB = (bY1 + bY2) * 0.5f;

        int gxA = min(max((int)(cxA * inv_s), 0), Wl - 1);
        int gyA = min(max((int)(cyA * inv_s), 0), Wl - 1);
        int gxB = min(max((int)(cxB * inv_s), 0), Wl - 1);
        int gyB = min(max((int)(cyB * inv_s), 0), Wl - 1);
        if (!vA) { gxA = 0; gyA = 0; }            // safe addresses when invalid
        if (!vB) { gxB = 0; gyB = 0; }

        // ---- issue all 4 gathers (MLP 4) + early adj prefetch ----
        const float* rbA = rp + (size_t)b * 64 * HW + (size_t)gyA * Wl + gxA;
        const float* rbB = rp + (size_t)b * 64 * HW + (size_t)gyB * Wl + gxB;
        float pA0 = rbA[(size_t)lane * HW];
        float pA1 = rbA[(size_t)(lane + 32) * HW];
        float pB0 = rbB[(size_t)lane * HW];
        float pB1 = rbB[(size_t)(lane + 32) * HW];

        int cidA = (int)fmaxf(tA0, 0.0f);
        int cidB = (int)fmaxf(tB0, 0.0f);
        float l0A = 0.0f, lcA = 0.0f, l0B = 0.0f, lcB = 0.0f;
        if (lane == 0) {                          // prefetch before shfl chains
            const float* lpA = cp + ((size_t)b * HW + (size_t)(gyA * Wl + gxA)) * 4;
            const float* lpB = cp + ((size_t)b * HW + (size_t)(gyB * Wl + gxB)) * 4;
            l0A = lpA[0]; lcA = lpA[cidA];
            l0B = lpB[0]; lcB = lpB[cidB];
        }

        // ---- treg values ----
        float trA0 = (cxA - (float)gxA * s) * inv_s;
        float trA1 = (cyA - (float)gyA * s) * inv_s;
        float trA2 = (aX2 - aX1) * inv_s;
        float trA3 = (aY2 - aY1) * inv_s;
        float trB0 = (cxB - (float)gxB * s) * inv_s;
        float trB1 = (cyB - (float)gyB * s) * inv_s;
        float trB2 = (bX2 - bX1) * inv_s;
        float trB3 = (bY2 - bY1) * inv_s;

        float selA0 = (lane < 16) ? trA0 : trA1;
        float selA1 = (lane < 16) ? trA2 : trA3;
        float selB0 = (lane < 16) ? trB0 : trB1;
        float selB1 = (lane < 16) ? trB2 : trB3;

        // ---- dfl sums (two independent chains pipeline) ----
        float dA = fabsf(pA0 - selA0) + fabsf(pA1 - selA1);
        float dB = fabsf(pB0 - selB0) + fabsf(pB1 - selB1);
        #pragma unroll
        for (int o = 16; o > 0; o >>= 1) {
            dA += __shfl_xor_sync(FULL_MASK, dA, o);
            dB += __shfl_xor_sync(FULL_MASK, dB, o);
        }

        // ---- 16-lane segmented sums (four independent chains) ----
        float qA0 = pA0, qA1 = pA1, qB0 = pB0, qB1 = pB1;
        #pragma unroll
        for (int o = 8; o > 0; o >>= 1) {
            qA0 += __shfl_xor_sync(FULL_MASK, qA0, o);
            qA1 += __shfl_xor_sync(FULL_MASK, qA1, o);
            qB0 += __shfl_xor_sync(FULL_MASK, qB0, o);
            qB1 += __shfl_xor_sync(FULL_MASK, qB1, o);
        }
        float mA1 = __shfl_sync(FULL_MASK, qA0, 16);
        float mA3 = __shfl_sync(FULL_MASK, qA1, 16);
        float mB1 = __shfl_sync(FULL_MASK, qB0, 16);
        float mB3 = __shfl_sync(FULL_MASK, qB1, 16);

        if (lane == 0) {
            const float i16 = 1.0f / 16.0f;
            float adj = 0.0f, box = 0.0f, dfl = 0.0f;
            int   cnt = 0;
            if (vA) {
                adj += (l0A - lcA) * invHW;
                box += (fabsf(qA0 * i16 - trA0) + fabsf(mA1 * i16 - trA1) +
                        fabsf(qA1 * i16 - trA2) + fabsf(mA3 * i16 - trA3)) * 0.25f;
                dfl += dA * (1.0f / 64.0f);
                cnt++;
            }
            if (vB) {
                adj += (l0B - lcB) * invHW;
                box += (fabsf(qB0 * i16 - trB0) + fabsf(mB1 * i16 - trB1) +
                        fabsf(qB1 * i16 - trB2) + fabsf(mB3 * i16 - trB3)) * 0.25f;
                dfl += dB * (1.0f / 64.0f);
                cnt++;
            }
            if (vA || vB) {
                atomicAdd(&s_acc[0], (double)adj);
                atomicAdd(&s_acc[1], (double)box);
                atomicAdd(&s_acc[2], (double)dfl);
                if (lvl == 0 && cnt) atomicAdd(&s_cnt, cnt);
            }
        }
        __syncthreads();
        if (tid == 0) {
            atomicAdd(&g_adj, s_acc[0]);
            atomicAdd(&g_box, s_acc[1]);
            atomicAdd(&g_dfl, s_acc[2]);
            if (s_cnt) atomicAdd(&g_cnt[b], s_cnt);
        }
    } else {
        // ------------------- cls base term (streaming) --------------------
        int cb = blockIdx.x - TGT_BLOCKS;

        auto rowval = [](const float4 v) -> float {
            float m  = fmaxf(fmaxf(v.x, v.y), fmaxf(v.z, v.w));
            float se = __expf(v.x - m) + __expf(v.y - m) +
                       __expf(v.z - m) + __expf(v.w - m);
            return (m + __logf(se)) - v.x;
        };

        float scaled;
        int b;
        if (cb < 128) {
            b = cb >> 2;
            const float4* base = reinterpret_cast<const float4*>(c0) +
                                 (size_t)b * 16384 + (size_t)(cb & 3) * 4096 + tid;
            float acc = 0.0f;
            #pragma unroll
            for (int i = 0; i < 16; i++)
                acc += rowval(base[(size_t)i * 256]);
            scaled = acc * (1.0f / 16384.0f);
        } else {
            b = cb - 128;
            const float4* b1 = reinterpret_cast<const float4*>(c1) + (size_t)b * 4096 + tid;
            const float4* b2 = reinterpret_cast<const float4*>(c2) + (size_t)b * 1024 + tid;
            const float4* b3 = reinterpret_cast<const float4*>(c3) + (size_t)b * 256  + tid;
            float a1 = 0.0f, a2 = 0.0f, a3;
            #pragma unroll
            for (int i = 0; i < 16; i++)
                a1 += rowval(b1[(size_t)i * 256]);
            #pragma unroll
            for (int i = 0; i < 4; i++)
                a2 += rowval(b2[(size_t)i * 256]);
            a3 = rowval(b3[0]);
            scaled = a1 * (1.0f / 4096.0f) + a2 * (1.0f / 1024.0f)
                   + a3 * (1.0f / 256.0f);
        }

        #pragma unroll
        for (int o = 16; o > 0; o >>= 1)
            scaled += __shfl_xor_sync(FULL_MASK, scaled, o);

        __shared__ float wsum[8];
        int wid = tid >> 5;
        if ((tid & 31) == 0) wsum[wid] = scaled;
        __syncthreads();
        if (tid == 0) {
            double ssum = 0.0;
            #pragma unroll
            for (int i = 0; i < 8; i++) ssum += (double)wsum[i];
            atomicAdd(&g_S[b], ssum);
        }
    }

    // ------------------- last-block finalize + reset -------------------
    __shared__ bool is_last;
    __threadfence();
    if (tid == 0) {
        unsigned int v = atomicAdd(&g_arrive, 1u);
        is_last = (v == (unsigned)(TOTAL_BLOCKS - 1));
    }
    __syncthreads();

    if (is_last) {
        __threadfence();   // acquire: see all other blocks' accumulator writes
        if (tid == 0) {
            double cls = g_adj;
            #pragma unroll
            for (int b2 = 0; b2 < BATCH; b2++)
                cls += (double)g_cnt[b2] * g_S[b2];
            float clsf = (float)cls;
            float boxf = (float)g_box;
            float dflf = (float)g_dfl;
            out[0] = 0.3f * clsf + 8.0f * boxf + 1.5f * dflf;
            out[1] = clsf;
            out[2] = boxf;
            out[3] = dflf;
        }
        __syncthreads();   // output computed before anyone resets state
        if (tid < BATCH)     { g_S[tid] = 0.0; g_cnt[tid] = 0; }
        if (tid == BATCH)      g_adj = 0.0;
        if (tid == BATCH + 1)  g_box = 0.0;
        if (tid == BATCH + 2)  g_dfl = 0.0;
        if (tid == BATCH + 3)  g_arrive = 0u;
    }
}

extern "C" void kernel_launch(void* const* d_in, const int* in_sizes, int n_in,
                              void* d_out, int out_size)
{
    // Map inputs by element count (order-agnostic). Ambiguous pairs resolved
    // by first-occurrence (cls precedes its reg twin in both grouped and
    // interleaved metadata orders).
    const float *c0 = nullptr, *c1 = nullptr, *c2 = nullptr, *c3 = nullptr;
    const float *r0 = nullptr, *r1 = nullptr, *r2 = nullptr, *r3 = nullptr;
    const float *tg = nullptr;
    int seen2097152 = 0, seen524288 = 0;

    for (int i = 0; i < n_in; i++) {
        const float* p = (const float*)d_in[i];
        switch (in_sizes[i]) {
            case 33554432: r0 = p; break;
            case 8388608:  r1 = p; break;
            case 131072:   c2 = p; break;
            case 32768:    c3 = p; break;
            case 10240:    tg = p; break;
            case 2097152:
                if (seen2097152++ == 0) c0 = p; else r2 = p;
                break;
            case 524288:
                if (seen524288++ == 0) c1 = p; else r3 = p;
                break;
            default: break;
        }
    }

    float* out = (float*)d_out;
    yolo_fused_kernel<<<TOTAL_BLOCKS, 256>>>(c0, c1, c2, c3,
                                             r0, r1, r2, r3, tg, out);
}